// round 5
// baseline (speedup 1.0000x reference)
#include <cuda_runtime.h>
#include <cstdint>

// MoEVM_62380105007239 — soft-ALU over one-hot byte encodings.
// R5: fused kernel, one read stream + one write stream per warp (R4), but
// the block-wide __syncthreads() is replaced with per-pair named barriers
// (bar.sync id,64) so each warp pair starts its write stream the moment its
// own reads land — no per-block read->write convoy at the memory controller.
//   warp 2g   (role 0): reads a[e], writes add-output[e]
//   warp 2g+1 (role 1): reads b[e], writes xor-output[e]
// Output values: 1.0 at result byte, exp(-100) (fp32 subnormal) at bytes
// sharing a nibble, 0 elsewhere — exactly what SCALE=100 softmax yields.

static __device__ __forceinline__ float onehot_val(int j, int s, float tiny) {
    if (j == s) return 1.0f;
    if (((j ^ s) & 0xF0) == 0 || ((j ^ s) & 0x0F) == 0) return tiny;
    return 0.0f;
}

__global__ void __launch_bounds__(256, 6) moe_alu_kernel(
    const float4* __restrict__ a4,
    const float4* __restrict__ b4,
    float4* __restrict__ o4,
    int B)
{
    __shared__ unsigned sm[4][2];            // [pair g][role]

    const int wid  = threadIdx.x >> 5;       // 0..7
    const int lane = threadIdx.x & 31;
    const int g    = wid >> 1;               // pair id 0..3
    const int role = wid & 1;                // 0: a / add-half, 1: b / xor-half
    const int e    = blockIdx.x * 4 + g;     // batch element
    if (e >= B) return;                      // partner warp exits identically

    // ── Read phase: one 4 KB sequential stream per warp ──
    const float4* __restrict__ src = (role == 0 ? a4 : b4) + (size_t)e * 256;

    // FMA decode: one-hot dot index == the index (index 0 contributes 0,
    // which is correct for the OR-pack). Slot s = r>>1 is compile-time
    // uniform per unrolled iteration.
    float acc[4] = {0.f, 0.f, 0.f, 0.f};
    #pragma unroll
    for (int r = 0; r < 8; r++) {
        const float4 x = __ldcs(src + lane + 32 * r);
        const float  j = (float)(lane * 4 + 128 * (r & 1));
        acc[r >> 1] += x.x * j + x.y * (j + 1.f)
                     + x.z * (j + 2.f) + x.w * (j + 3.f);
    }
    unsigned iv = (unsigned)(int)acc[0]
                | ((unsigned)(int)acc[1] << 8)
                | ((unsigned)(int)acc[2] << 16)
                | ((unsigned)(int)acc[3] << 24);
    const unsigned v = __reduce_or_sync(0xFFFFFFFFu, iv);
    if (lane == 0) sm[g][role] = v;

    // Pairwise named barrier: only the two warps of pair g participate
    // (64 threads). Ids 1..4 avoid the default barrier 0.
    asm volatile("bar.sync %0, 64;" :: "r"(g + 1) : "memory");

    const unsigned va = sm[g][0];
    const unsigned vb = sm[g][1];
    const unsigned res = (role == 0) ? (va + vb)   // LE carry chain == u32 add
                                     : (va ^ vb);  // bytewise xor

    const float TINY = 3.7200760e-44f;             // expf(-100), subnormal

    // ── Write phase: one 4 KB sequential stream per warp ──
    float4* __restrict__ dst = o4 + ((size_t)role * B + e) * 256;
    #pragma unroll
    for (int r = 0; r < 8; r++) {
        const int j  = lane * 4 + 128 * (r & 1);   // byte idx of component .x
        const int sb = (int)((res >> ((r >> 1) * 8)) & 255u);
        float4 o;
        o.x = onehot_val(j    , sb, TINY);
        o.y = onehot_val(j + 1, sb, TINY);
        o.z = onehot_val(j + 2, sb, TINY);
        o.w = onehot_val(j + 3, sb, TINY);
        __stcs(dst + lane + 32 * r, o);
    }
}

extern "C" void kernel_launch(void* const* d_in, const int* in_sizes, int n_in,
                              void* d_out, int out_size)
{
    const float4* a = (const float4*)d_in[0];
    const float4* b = (const float4*)d_in[1];
    float4* out = (float4*)d_out;

    const int B = in_sizes[0] / 1024;      // inputs are [B,4,256] floats
    const int blocks = (B + 3) / 4;        // 4 elements per 8-warp block
    moe_alu_kernel<<<blocks, 256>>>(a, b, out, B);
}